// round 8
// baseline (speedup 1.0000x reference)
#include <cuda_runtime.h>
#include <cuda_fp16.h>
#include <cstdint>

// ---------------- Problem constants ----------------
#define B_TOTAL   8192
#define F_DIM     64
#define NX        82
#define NY        67
#define NYP       96
#define P_TOTAL   (NX * NY)      // 5494
#define KP        64             // fp16 K
#define KSTEPS    (KP / 16)      // 4

// ---------------- Tile config ----------------
#define TILE_M    64
#define BT_PER_CTA 8
#define GRID_Y    (B_TOTAL / TILE_M / BT_PER_CTA)   // 16
#define ROWE      72             // W smem row stride in fp16 (144B)

// SMEM layout (bytes): W prologue image overlays DS0 (dead after reg hoist)
#define OFF_W     0
#define W_BYTES   (NYP * ROWE * 2)          // 13824
#define DS_STRIDE 68
#define DS_BYTES  (TILE_M * DS_STRIDE * 4)  // 17408
#define OFF_DS0   0
#define OFF_DS1   DS_BYTES                  // 17408
#define OFF_BIAS  (2 * DS_BYTES)            // 34816
#define SMEM_TOTAL (OFF_BIAS + 384)         // 35200 -> 3 CTAs/SM (reg-permitting)

// ---------------- Scratch (device globals; no allocation allowed) ----------------
// A in mma fragment order: [g32][ks][mf][lane] of uint4, g32 = 32-row group
#define AFRAG_U4  (B_TOTAL * KP * 2 / 16)   // 65536 uint4
__device__ __align__(16) uint4 g_Afrag[AFRAG_U4];
__device__ __align__(16) __half g_Wp[NX * NYP * KP];   // [x][96][64]

static __device__ __forceinline__ uint32_t smem_u32(const void* p) {
    return (uint32_t)__cvta_generic_to_shared(p);
}
static __device__ __forceinline__ void cp_async16(uint32_t dst, const void* src) {
    asm volatile("cp.async.cg.shared.global [%0], [%1], 16;" :: "r"(dst), "l"(src));
}
static __device__ __forceinline__ uint32_t packh2(float a, float b) {
    __half2 h = __floats2half2_rn(a, b);
    return *(uint32_t*)&h;
}

// ---------------- Merged prep kernel (unchanged layout) ----------------
#define W_CHUNKS (NX * NYP * 16)                 // 125952
#define PREP_THREADS (AFRAG_U4 + W_CHUNKS)       // 191488
#define PREP_BLOCKS ((PREP_THREADS + 255) / 256) // 749
__global__ void prep_kernel(const float* __restrict__ in, const float* __restrict__ W) {
    int idx = blockIdx.x * 256 + threadIdx.x;
    if (idx < AFRAG_U4) {
        // decompose: [g32][ks(2)][mf(1)][lane(5)]
        int lane = idx & 31;
        int rest = idx >> 5;
        int mf = rest & 1;
        int ks = (rest >> 1) & 3;
        int g32 = rest >> 3;
        int b0 = g32 * 32 + mf * 16 + (lane >> 2);
        int k0 = ks * 16 + (lane & 3) * 2;
        const float* p = in + b0 * F_DIM + k0;
        float2 v0 = *(const float2*)p;
        float2 v1 = *(const float2*)(p + 8 * F_DIM);
        float2 v2 = *(const float2*)(p + 8);
        float2 v3 = *(const float2*)(p + 8 * F_DIM + 8);
        uint4 o;
        o.x = packh2(v0.x, v0.y);
        o.y = packh2(v1.x, v1.y);
        o.z = packh2(v2.x, v2.y);
        o.w = packh2(v3.x, v3.y);
        g_Afrag[idx] = o;
    } else if (idx < PREP_THREADS) {
        int j = idx - AFRAG_U4;
        int x = j / (NYP * 16);
        int rem = j - x * (NYP * 16);
        int y = rem >> 4;
        int c4 = rem & 15;
        uint2 pack = {0u, 0u};
        if (y < NY) {
            float4 v = *(const float4*)(W + ((size_t)(y * NX + x) * F_DIM + c4 * 4));
            pack.x = packh2(v.x, v.y);
            pack.y = packh2(v.z, v.w);
        }
        *(uint2*)(g_Wp + ((size_t)(x * NYP + y) * KP + c4 * 4)) = pack;
    }
}

// ---------------- GEMM kernel ----------------
// Grid: (x = 0..81, by = 0..15). Block: 256 threads (8 warps, 2M x 4N).
// Warp tile: 32 rows x 24 cols. W register-resident; A direct LDG; 1 sync/tile.
__global__ __launch_bounds__(256, 3)
void gemm_kernel(const float* __restrict__ bias, float* __restrict__ out) {
    extern __shared__ __align__(16) char smem[];
    float* bias_s = (float*)(smem + OFF_BIAS);   // [96], zero-padded

    const int x  = blockIdx.x;
    const int by = blockIdx.y;
    const int tid = threadIdx.x;
    const int lane = tid & 31;
    const int warp = tid >> 5;
    const int warpM = warp & 1;   // 0..1 (32-row half)
    const int warpN = warp >> 1;  // 0..3 (24-col slice)
    const uint32_t sbase = smem_u32(smem);

    // ---- Prologue: W tile -> smem -> registers (once per CTA) ----
    {
        const char* srcW = (const char*)(g_Wp + (size_t)x * NYP * KP);
        #pragma unroll
        for (int i = tid; i < NYP * 8; i += 256) {
            int r = i >> 3;
            int c = i & 7;
            cp_async16(sbase + OFF_W + r * 144 + c * 16, srcW + r * 128 + c * 16);
        }
        asm volatile("cp.async.commit_group;" ::: "memory");
    }
    if (tid < NYP) bias_s[tid] = (tid < NY) ? bias[tid * NX + x] : 0.0f;
    asm volatile("cp.async.wait_group 0;" ::: "memory");
    __syncthreads();

    // W fragments: 24 cols = frags 0,1 via x4 + frag 2 via x2. wreg[ks][frag][kh]
    uint32_t wreg[KSTEPS][3][2];
    {
        const uint32_t b4 = sbase + OFF_W
            + ((warpN * 24 + (lane & 15)) * ROWE + (lane >> 4) * 8) * 2;
        const uint32_t b2 = sbase + OFF_W
            + ((warpN * 24 + 16 + (lane & 7)) * ROWE + ((lane >> 3) & 1) * 8) * 2;
        #pragma unroll
        for (int ks = 0; ks < KSTEPS; ks++) {
            uint32_t w0, w1, w2, w3, w4, w5;
            asm volatile("ldmatrix.sync.aligned.m8n8.x4.shared.b16 {%0,%1,%2,%3}, [%4];"
                         : "=r"(w0), "=r"(w1), "=r"(w2), "=r"(w3)
                         : "r"(b4 + ks * 32));
            asm volatile("ldmatrix.sync.aligned.m8n8.x2.shared.b16 {%0,%1}, [%2];"
                         : "=r"(w4), "=r"(w5)
                         : "r"(b2 + ks * 32));
            wreg[ks][0][0] = w0; wreg[ks][0][1] = w2;
            wreg[ks][1][0] = w1; wreg[ks][1][1] = w3;
            wreg[ks][2][0] = w4; wreg[ks][2][1] = w5;
        }
    }
    __syncthreads();   // W smem image dead; DS0 may overwrite

    // d-frag output coordinates
    const int r0 = warpM * 32 + (lane >> 2);
    const int cb = warpN * 24 + (lane & 3) * 2;

    for (int t = 0; t < BT_PER_CTA; t++) {
        const int bt = by * BT_PER_CTA + t;                  // 64-row tile index
        const int g32 = bt * 2 + warpM;
        const uint4* aF = g_Afrag + ((size_t)g32 << 8) + lane;
        float* Ds = (float*)(smem + ((t & 1) ? OFF_DS1 : OFF_DS0));

        float d[2][3][4];
        #pragma unroll
        for (int mf = 0; mf < 2; mf++)
            #pragma unroll
            for (int nf = 0; nf < 3; nf++)
                #pragma unroll
                for (int j = 0; j < 4; j++) d[mf][nf][j] = 0.0f;

        #pragma unroll
        for (int ks = 0; ks < KSTEPS; ks++) {
            uint4 a0 = aF[(ks * 2 + 0) * 32];
            uint4 a1 = aF[(ks * 2 + 1) * 32];
            const uint32_t* am[2] = { (const uint32_t*)&a0, (const uint32_t*)&a1 };
            #pragma unroll
            for (int mf = 0; mf < 2; mf++) {
                #pragma unroll
                for (int nf = 0; nf < 3; nf++) {
                    float* dd = d[mf][nf];
                    asm volatile(
                        "mma.sync.aligned.m16n8k16.row.col.f32.f16.f16.f32 "
                        "{%0,%1,%2,%3}, {%4,%5,%6,%7}, {%8,%9}, {%0,%1,%2,%3};"
                        : "+f"(dd[0]), "+f"(dd[1]), "+f"(dd[2]), "+f"(dd[3])
                        : "r"(am[mf][0]), "r"(am[mf][1]), "r"(am[mf][2]), "r"(am[mf][3]),
                          "r"(wreg[ks][nf][0]), "r"(wreg[ks][nf][1]));
                }
            }
        }

        // ---- Stage to SMEM buffer (bias folded, float2 stores) ----
        #pragma unroll
        for (int nf = 0; nf < 3; nf++) {
            const int y = cb + nf * 8;   // even
            const float b0 = bias_s[y];
            const float b1 = bias_s[y + 1];
            #pragma unroll
            for (int mf = 0; mf < 2; mf++) {
                const int rA = r0 + mf * 16;
                if (y + 1 < NY) {
                    *(float2*)&Ds[rA * DS_STRIDE + y] =
                        make_float2(d[mf][nf][0] + b0, d[mf][nf][1] + b1);
                    *(float2*)&Ds[(rA + 8) * DS_STRIDE + y] =
                        make_float2(d[mf][nf][2] + b0, d[mf][nf][3] + b1);
                } else if (y < NY) {
                    Ds[rA * DS_STRIDE + y]       = d[mf][nf][0] + b0;
                    Ds[(rA + 8) * DS_STRIDE + y] = d[mf][nf][2] + b0;
                }
            }
        }
        __syncthreads();   // ONE sync per tile (double buffer covers reuse)

        // ---- Coalesced writeout: warp = 8 rows, lane = col ----
        {
            float* gRow = out + (size_t)(bt * TILE_M + warp * 8) * P_TOTAL + x * NY + lane;
            const float* sRow = Ds + (warp * 8) * DS_STRIDE + lane;
            #pragma unroll
            for (int rr = 0; rr < 8; rr++) {
                float v0 = sRow[0];
                float v1 = sRow[32];
                gRow[0]  = v0;
                gRow[32] = v1;
                if (lane < 3) gRow[64] = sRow[64];
                sRow += DS_STRIDE;
                gRow += P_TOTAL;
            }
        }
        // no trailing sync: next tile stages into the other buffer
    }
}

// ---------------- Launch ----------------
extern "C" void kernel_launch(void* const* d_in, const int* in_sizes, int n_in,
                              void* d_out, int out_size) {
    const float* inputs = nullptr;  // 8192*64
    const float* W = nullptr;       // 5494*64
    const float* bias = nullptr;    // 5494
    for (int i = 0; i < n_in; i++) {
        if (in_sizes[i] == B_TOTAL * F_DIM) inputs = (const float*)d_in[i];
        else if (in_sizes[i] == P_TOTAL * F_DIM) W = (const float*)d_in[i];
        else if (in_sizes[i] == P_TOTAL) bias = (const float*)d_in[i];
    }
    float* out = (float*)d_out;

    prep_kernel<<<PREP_BLOCKS, 256>>>(inputs, W);

    cudaFuncSetAttribute(gemm_kernel, cudaFuncAttributeMaxDynamicSharedMemorySize, SMEM_TOTAL);
    dim3 grid(NX, GRID_Y);   // (82, 16)
    gemm_kernel<<<grid, 256, SMEM_TOTAL>>>(bias, out);
}